// round 9
// baseline (speedup 1.0000x reference)
#include <cuda_runtime.h>
#include <cstdint>

#define BATCH 16
#define NTOK  16384
#define CH    64
#define NKV   256

// scratch (allocation-free)
__device__ float g_k[BATCH * NKV * CH];     // K natural [b][t][d] (tf32-rounded)
__device__ float g_v[BATCH * CH * NKV];     // V transposed [b][d][t] (tf32-rounded)
__device__ float g_wqT[64 * 64];            // Wq^T [d][c] (tf32)
__device__ float g_woT[64 * 64];            // Wo^T [e][d] (tf32)
__device__ float g_wkvT[128 * 64];          // Wkv^T [o][c] (tf32)
__device__ float g_cwT[64 * 4096];          // conv_w^T [co][ij*64+ci] (tf32)

__device__ __forceinline__ uint32_t f2t(float x) {
    uint32_t u; asm("cvt.rna.tf32.f32 %0, %1;" : "=r"(u) : "f"(x)); return u;
}
__device__ __forceinline__ float f2tf(float x) { return __uint_as_float(f2t(x)); }

__device__ __forceinline__ void mma8(float* d, const uint32_t* a, const uint32_t* b) {
    asm volatile(
        "mma.sync.aligned.m16n8k8.row.col.f32.tf32.tf32.f32 "
        "{%0,%1,%2,%3},{%4,%5,%6,%7},{%8,%9},{%0,%1,%2,%3};"
        : "+f"(d[0]), "+f"(d[1]), "+f"(d[2]), "+f"(d[3])
        : "r"(a[0]), "r"(a[1]), "r"(a[2]), "r"(a[3]), "r"(b[0]), "r"(b[1]));
}

// --- scalar (natural layout) fragment loads: used by conv kernel ---
__device__ __forceinline__ void ldA(uint32_t* a, const float* pa, int s8) {
    a[0] = __float_as_uint(pa[0]);  a[1] = __float_as_uint(pa[s8]);
    a[2] = __float_as_uint(pa[4]);  a[3] = __float_as_uint(pa[s8 + 4]);
}
__device__ __forceinline__ void ldB(uint32_t* b, const float* pb) {
    b[0] = __float_as_uint(pb[0]);  b[1] = __float_as_uint(pb[4]);
}

// --- permuted-k layout helpers: logical k -> phys ((k&3)<<1)|(k>>2) per 8-group
// thread t4 then reads the contiguous pair {k0+2t4, k0+2t4+1} = logical {t4, t4+4}
// pa = &A[row * stride + k0 + 2*t4], s8 = 8*stride (row -> row+8)
__device__ __forceinline__ void ldA64(uint32_t* a, const float* pa, int s8) {
    float2 v0 = *(const float2*)pa;
    float2 v1 = *(const float2*)(pa + s8);
    a[0] = __float_as_uint(v0.x); a[2] = __float_as_uint(v0.y);
    a[1] = __float_as_uint(v1.x); a[3] = __float_as_uint(v1.y);
}
__device__ __forceinline__ void ldB64(uint32_t* b, const float* pb) {
    float2 v = *(const float2*)pb;
    b[0] = __float_as_uint(v.x); b[1] = __float_as_uint(v.y);
}
// stage a float4 of 4 consecutive logical k (quarter c4) into permuted layout
__device__ __forceinline__ void stPerm4(float* rowp, int c4, float4 v) {
    float* p = rowp + ((c4 >> 1) << 3) + (c4 & 1);
    p[0] = v.x; p[2] = v.y; p[4] = v.z; p[6] = v.w;
}
// epilogue: logical col pair (X*8+2t4, +1) -> physical (X*8+q, X*8+q+2)
__device__ __forceinline__ int permPair(int t4) { return ((t4 & 1) << 2) | (t4 >> 1); }

// ============================================================================
// prep: transpose + tf32-round all weight matrices
// ============================================================================
__global__ __launch_bounds__(256) void prep_kernel(
    const float* __restrict__ Wq, const float* __restrict__ Wo,
    const float* __restrict__ Wkv, const float* __restrict__ cw)
{
    int i = blockIdx.x * 256 + threadIdx.x;
    if (i < 4096) {
        int d = i >> 6, c = i & 63;
        g_wqT[i] = f2tf(Wq[c * 64 + d]);
    } else if (i < 8192) {
        int j = i - 4096, e = j >> 6, d = j & 63;
        g_woT[j] = f2tf(Wo[d * 64 + e]);
    } else if (i < 16384) {
        int j = i - 8192, o = j >> 6, c = j & 63;
        g_wkvT[j] = f2tf(Wkv[c * 128 + o]);
    } else if (i < 278528) {
        int j = i - 16384, co = j >> 12, k = j & 4095;
        g_cwT[j] = f2tf(cw[k * 64 + co]);
    }
}

// ============================================================================
// Kernel 1: strided conv (8x8, s8) + bias + LN + KV proj (unchanged from R6)
// ============================================================================
__global__ __launch_bounds__(256) void conv_kv_kernel(
    const float* __restrict__ x, const float* __restrict__ convb,
    const float* __restrict__ gamma, const float* __restrict__ beta,
    const float* __restrict__ bkv)
{
    __shared__ float sC[32 * 68];
    __shared__ float sB[128 * 68];
    __shared__ float aux[576];

    const int tid = threadIdx.x;
    const int w = tid >> 5, lane = tid & 31, g = lane >> 2, t4 = lane & 3;
    const int t0 = blockIdx.x * 32, b = t0 >> 8;
    const int mi = w & 1, m0 = mi * 16;

    const int tt = tid & 31, ci0 = (tid >> 5) * 8;
    const int gb = (t0 + tt) & 255, ph = gb >> 4, pw = gb & 15;
    const float* xb = x + (size_t)b * NTOK * CH;

    float acc1[2][4];
    #pragma unroll
    for (int n = 0; n < 2; n++) { acc1[n][0]=acc1[n][1]=acc1[n][2]=acc1[n][3]=0.f; }

    for (int ij = 0; ij < 64; ij++) {
        __syncthreads();
        {
            const int row = ph * 8 + (ij >> 3), col = pw * 8 + (ij & 7);
            const float* xr = xb + (size_t)(row * 128 + col) * CH + ci0;
            float4 v0 = *(const float4*)xr, v1 = *(const float4*)(xr + 4);
            *(float4*)&sC[tt * 68 + ci0]     = make_float4(f2tf(v0.x), f2tf(v0.y), f2tf(v0.z), f2tf(v0.w));
            *(float4*)&sC[tt * 68 + ci0 + 4] = make_float4(f2tf(v1.x), f2tf(v1.y), f2tf(v1.z), f2tf(v1.w));
        }
        #pragma unroll
        for (int r = 0; r < 4; r++) {
            int pos = tid + r * 256, co = pos >> 4, c4 = pos & 15;
            *(float4*)&sB[co * 68 + c4 * 4] =
                *(const float4*)&g_cwT[co * 4096 + ij * 64 + c4 * 4];
        }
        __syncthreads();
        #pragma unroll
        for (int k0 = 0; k0 < 64; k0 += 8) {
            uint32_t a[4]; ldA(a, &sC[(m0 + g) * 68 + k0 + t4], 544);
            #pragma unroll
            for (int n = 0; n < 2; n++) {
                uint32_t bb[2]; ldB(bb, &sB[(((w >> 1) * 2 + n) * 8 + g) * 68 + k0 + t4]);
                mma8(acc1[n], a, bb);
            }
        }
    }
    __syncthreads();
    #pragma unroll
    for (int n = 0; n < 2; n++) {
        int c0 = ((w >> 1) * 2 + n) * 8 + 2 * t4;
        float2 bc = *(const float2*)&convb[c0];
        *(float2*)&sC[(m0 + g) * 68 + c0]     = make_float2(acc1[n][0] + bc.x, acc1[n][1] + bc.y);
        *(float2*)&sC[(m0 + g + 8) * 68 + c0] = make_float2(acc1[n][2] + bc.x, acc1[n][3] + bc.y);
    }
    __syncthreads();
    #pragma unroll
    for (int r = 0; r < 8; r++) {
        int pos = tid + r * 256, o = pos >> 4, c4 = pos & 15;
        *(float4*)&sB[o * 68 + c4 * 4] = *(const float4*)&g_wkvT[o * 64 + c4 * 4];
    }
    {
        int tok = tid & 31, pr = tid >> 5;
        float4 u0 = *(float4*)&sC[tok * 68 + pr * 8];
        float4 u1 = *(float4*)&sC[tok * 68 + pr * 8 + 4];
        float s  = u0.x + u0.y + u0.z + u0.w + u1.x + u1.y + u1.z + u1.w;
        float sq = u0.x*u0.x + u0.y*u0.y + u0.z*u0.z + u0.w*u0.w
                 + u1.x*u1.x + u1.y*u1.y + u1.z*u1.z + u1.w*u1.w;
        aux[pr * 32 + tok] = s; aux[256 + pr * 32 + tok] = sq;
    }
    __syncthreads();
    if (tid < 32) {
        float s = 0.f, sq = 0.f;
        #pragma unroll
        for (int p = 0; p < 8; p++) { s += aux[p * 32 + tid]; sq += aux[256 + p * 32 + tid]; }
        float mean = s * (1.f / 64.f);
        float var  = sq * (1.f / 64.f) - mean * mean;
        aux[512 + tid] = mean; aux[544 + tid] = rsqrtf(var + 1e-5f);
    }
    __syncthreads();
    {
        int tok = tid & 31, pr = tid >> 5;
        float mean = aux[512 + tok], r = aux[544 + tok];
        #pragma unroll
        for (int u = 0; u < 8; u++) {
            int c = pr * 8 + u;
            float v = sC[tok * 68 + c];
            sC[tok * 68 + c] = f2tf((v - mean) * r * __ldg(gamma + c) + __ldg(beta + c));
        }
    }
    __syncthreads();
    float acc2[4][4];
    #pragma unroll
    for (int n = 0; n < 4; n++) { acc2[n][0]=acc2[n][1]=acc2[n][2]=acc2[n][3]=0.f; }
    #pragma unroll
    for (int k0 = 0; k0 < 64; k0 += 8) {
        uint32_t a[4]; ldA(a, &sC[(m0 + g) * 68 + k0 + t4], 544);
        #pragma unroll
        for (int n = 0; n < 4; n++) {
            uint32_t bb[2]; ldB(bb, &sB[(((w >> 1) * 4 + n) * 8 + g) * 68 + k0 + t4]);
            mma8(acc2[n], a, bb);
        }
    }
    const int tloc = t0 & 255;
    #pragma unroll
    for (int n = 0; n < 4; n++) {
        int c0 = ((w >> 1) * 4 + n) * 8 + 2 * t4;
        float bk0 = __ldg(bkv + c0), bk1 = __ldg(bkv + c0 + 1);
        #pragma unroll
        for (int h = 0; h < 2; h++) {
            int row = m0 + g + h * 8;
            float r0 = f2tf(acc2[n][2 * h + 0] + bk0);
            float r1 = f2tf(acc2[n][2 * h + 1] + bk1);
            if (c0 < 64) {
                g_k[(size_t)(t0 + row) * 64 + c0]     = r0;
                g_k[(size_t)(t0 + row) * 64 + c0 + 1] = r1;
            } else {
                g_v[(size_t)(b * 64 + c0 - 64) * 256 + tloc + row] = r0;
                g_v[(size_t)(b * 64 + c0 - 63) * 256 + tloc + row] = r1;
            }
        }
    }
}

// ============================================================================
// Kernel 2: 64-query tile, 512 threads / 16 warps, permuted-k LDS.64 operands
// grid = (256, 16), ~188 KB dynamic smem
// ============================================================================
__global__ __launch_bounds__(512) void attn_kernel(
    const float* __restrict__ x, const float* __restrict__ bq,
    const float* __restrict__ bo, float* __restrict__ out)
{
    extern __shared__ float sm[];
    float* sX  = sm;             // 64x68 : X [tok][c] perm
    float* sWt = sm + 4352;      // 64x68 : WqT perm, later WoT perm
    float* sQ  = sm + 8704;      // 64x68 : Q perm (pre-scaled), later O perm
    float* sK  = sm + 13056;     // 256x68: K perm; later Vt [d][j] 64x260 perm
    float* sS  = sm + 30464;     // 64x260: S/P [tok][j] perm-in-j
    float* aux = sm + 47104;     // 512 pmax + 512 psum + 64 (gmax -> invl)

    const int tid = threadIdx.x;
    const int w = tid >> 5, lane = tid & 31, g = lane >> 2, t4 = lane & 3;
    const int b = blockIdx.y, q0 = blockIdx.x * 64;
    const int q2 = permPair(t4);

    // ---- stage X (tf32 + perm), WqT (perm), K (perm) ----
    #pragma unroll
    for (int r = 0; r < 2; r++) {
        int pos = tid + r * 512, tok = pos >> 4, c4 = pos & 15;
        float4 v = *(const float4*)&x[((size_t)(b * NTOK + q0 + tok)) * 64 + c4 * 4];
        stPerm4(&sX[tok * 68], c4, make_float4(f2tf(v.x), f2tf(v.y), f2tf(v.z), f2tf(v.w)));
    }
    #pragma unroll
    for (int r = 0; r < 2; r++) {
        int pos = tid + r * 512, d = pos >> 4, c4 = pos & 15;
        stPerm4(&sWt[d * 68], c4, *(const float4*)&g_wqT[d * 64 + c4 * 4]);
    }
    #pragma unroll
    for (int r = 0; r < 8; r++) {
        int pos = tid + r * 512, j = pos >> 4, c4 = pos & 15;
        stPerm4(&sK[j * 68], c4, *(const float4*)&g_k[(size_t)b * 16384 + j * 64 + c4 * 4]);
    }
    __syncthreads();

    // ---- GEMM1: Q = (X WqT^T + bq)*0.125 -> sQ perm  (warp: 1m x 2n8) ----
    {
        const int mi = w & 3, ng = w >> 2, m0 = mi * 16;
        float acc[2][4];
        #pragma unroll
        for (int n = 0; n < 2; n++) { acc[n][0]=acc[n][1]=acc[n][2]=acc[n][3]=0.f; }
        #pragma unroll
        for (int k0 = 0; k0 < 64; k0 += 8) {
            uint32_t a[4]; ldA64(a, &sX[(m0 + g) * 68 + k0 + 2 * t4], 544);
            #pragma unroll
            for (int n = 0; n < 2; n++) {
                uint32_t bb[2]; ldB64(bb, &sWt[((ng * 2 + n) * 8 + g) * 68 + k0 + 2 * t4]);
                mma8(acc[n], a, bb);
            }
        }
        #pragma unroll
        for (int n = 0; n < 2; n++) {
            int gbs = (ng * 2 + n) * 8;
            float b0 = __ldg(bq + gbs + 2 * t4), b1 = __ldg(bq + gbs + 2 * t4 + 1);
            float* p0 = &sQ[(m0 + g) * 68 + gbs + q2];
            float* p1 = &sQ[(m0 + g + 8) * 68 + gbs + q2];
            p0[0] = f2tf((acc[n][0] + b0) * 0.125f); p0[2] = f2tf((acc[n][1] + b1) * 0.125f);
            p1[0] = f2tf((acc[n][2] + b0) * 0.125f); p1[2] = f2tf((acc[n][3] + b1) * 0.125f);
        }
    }
    __syncthreads();

    // ---- GEMM2: S = Q K^T (m64 n256 k64), warp tile 32x32 (2m x 4n8) ----
    {
        const int mi2 = w & 1, ng2 = w >> 1;
        float acc[2][4][4];
        #pragma unroll
        for (int mt = 0; mt < 2; mt++)
            #pragma unroll
            for (int n = 0; n < 4; n++) { acc[mt][n][0]=acc[mt][n][1]=acc[mt][n][2]=acc[mt][n][3]=0.f; }
        #pragma unroll
        for (int k0 = 0; k0 < 64; k0 += 8) {
            uint32_t a0[4], a1[4];
            ldA64(a0, &sQ[(mi2 * 32 + g) * 68 + k0 + 2 * t4], 544);
            ldA64(a1, &sQ[(mi2 * 32 + 16 + g) * 68 + k0 + 2 * t4], 544);
            #pragma unroll
            for (int n = 0; n < 4; n++) {
                uint32_t bb[2]; ldB64(bb, &sK[((ng2 * 4 + n) * 8 + g) * 68 + k0 + 2 * t4]);
                mma8(acc[0][n], a0, bb);
                mma8(acc[1][n], a1, bb);
            }
        }
        #pragma unroll
        for (int mt = 0; mt < 2; mt++) {
            int r0 = mi2 * 32 + mt * 16 + g;
            #pragma unroll
            for (int n = 0; n < 4; n++) {
                int gbs = (ng2 * 4 + n) * 8;
                float* p0 = &sS[r0 * 260 + gbs + q2];
                float* p1 = &sS[(r0 + 8) * 260 + gbs + q2];
                p0[0] = acc[mt][n][0]; p0[2] = acc[mt][n][1];
                p1[0] = acc[mt][n][2]; p1[2] = acc[mt][n][3];
            }
        }
    }
    __syncthreads();

    // ---- stage Vt (perm in j, over sK) + WoT (perm, over sWt) ----
    #pragma unroll
    for (int r = 0; r < 8; r++) {
        int pos = tid + r * 512, d = pos >> 6, j4 = pos & 63;
        stPerm4(&sK[d * 260], j4, *(const float4*)&g_v[(size_t)b * 16384 + d * 256 + j4 * 4]);
    }
    #pragma unroll
    for (int r = 0; r < 2; r++) {
        int pos = tid + r * 512, e = pos >> 4, c4 = pos & 15;
        stPerm4(&sWt[e * 68], c4, *(const float4*)&g_woT[e * 64 + c4 * 4]);
    }

    // ---- softmax (8 threads/token, 32 j each; j order permuted = harmless) ----
    const int tok = tid & 63, pr = tid >> 6;
    {
        const float* sr = &sS[tok * 260 + pr * 32];
        float m = -1e30f;
        #pragma unroll
        for (int i = 0; i < 8; i++) {
            float4 v = *(const float4*)&sr[i * 4];
            m = fmaxf(m, fmaxf(fmaxf(v.x, v.y), fmaxf(v.z, v.w)));
        }
        aux[pr * 64 + tok] = m;
    }
    __syncthreads();
    if (tid < 64) {
        float m = aux[tid];
        #pragma unroll
        for (int p = 1; p < 8; p++) m = fmaxf(m, aux[p * 64 + tid]);
        aux[1024 + tid] = m;
    }
    __syncthreads();
    {
        float m = aux[1024 + tok];
        float* sr = &sS[tok * 260 + pr * 32];
        float s = 0.f;
        #pragma unroll
        for (int i = 0; i < 8; i++) {
            float4 v = *(float4*)&sr[i * 4];
            v.x = __expf(v.x - m); v.y = __expf(v.y - m);
            v.z = __expf(v.z - m); v.w = __expf(v.w - m);
            s += v.x + v.y + v.z + v.w;
            *(float4*)&sr[i * 4] = make_float4(f2tf(v.x), f2tf(v.y), f2tf(v.z), f2tf(v.w));
        }
        aux[512 + pr * 64 + tok] = s;
    }
    __syncthreads();
    if (tid < 64) {
        float s = 0.f;
        #pragma unroll
        for (int p = 0; p < 8; p++) s += aux[512 + p * 64 + tid];
        aux[1024 + tid] = 1.f / s;   // overwrite gmax with 1/l
    }
    __syncthreads();

    // ---- GEMM3: O = (P Vt^T) * invl (m64 n64 k256), warp 1m x 2n8 ----
    {
        const int mi = w & 3, ng = w >> 2, m0 = mi * 16;
        float acc[2][4];
        #pragma unroll
        for (int n = 0; n < 2; n++) { acc[n][0]=acc[n][1]=acc[n][2]=acc[n][3]=0.f; }
        #pragma unroll
        for (int k0 = 0; k0 < 256; k0 += 8) {
            uint32_t a[4]; ldA64(a, &sS[(m0 + g) * 260 + k0 + 2 * t4], 2080);
            #pragma unroll
            for (int n = 0; n < 2; n++) {
                uint32_t bb[2]; ldB64(bb, &sK[((ng * 2 + n) * 8 + g) * 260 + k0 + 2 * t4]);
                mma8(acc[n], a, bb);
            }
        }
        float li0 = aux[1024 + m0 + g], li1 = aux[1024 + m0 + g + 8];
        #pragma unroll
        for (int n = 0; n < 2; n++) {
            int gbs = (ng * 2 + n) * 8;
            float* p0 = &sQ[(m0 + g) * 68 + gbs + q2];
            float* p1 = &sQ[(m0 + g + 8) * 68 + gbs + q2];
            p0[0] = f2tf(acc[n][0] * li0); p0[2] = f2tf(acc[n][1] * li0);
            p1[0] = f2tf(acc[n][2] * li1); p1[2] = f2tf(acc[n][3] * li1);
        }
    }
    __syncthreads();

    // ---- GEMM4: Y = O WoT^T + bo -> gmem (natural layout) ----
    {
        const int mi = w & 3, ng = w >> 2, m0 = mi * 16;
        float acc[2][4];
        #pragma unroll
        for (int n = 0; n < 2; n++) { acc[n][0]=acc[n][1]=acc[n][2]=acc[n][3]=0.f; }
        #pragma unroll
        for (int k0 = 0; k0 < 64; k0 += 8) {
            uint32_t a[4]; ldA64(a, &sQ[(m0 + g) * 68 + k0 + 2 * t4], 544);
            #pragma unroll
            for (int n = 0; n < 2; n++) {
                uint32_t bb[2]; ldB64(bb, &sWt[((ng * 2 + n) * 8 + g) * 68 + k0 + 2 * t4]);
                mma8(acc[n], a, bb);
            }
        }
        #pragma unroll
        for (int n = 0; n < 2; n++) {
            int c0 = (ng * 2 + n) * 8 + 2 * t4;
            float2 bb = *(const float2*)&bo[c0];
            size_t rb = ((size_t)(b * NTOK + q0 + m0 + g)) * 64;
            *(float2*)&out[rb + c0]          = make_float2(acc[n][0] + bb.x, acc[n][1] + bb.y);
            *(float2*)&out[rb + 8 * 64 + c0] = make_float2(acc[n][2] + bb.x, acc[n][3] + bb.y);
        }
    }
}

extern "C" void kernel_launch(void* const* d_in, const int* in_sizes, int n_in,
                              void* d_out, int out_size)
{
    const float* inputs = (const float*)d_in[0];
    const float* Wq     = (const float*)d_in[1];
    const float* bq     = (const float*)d_in[2];
    const float* Wkv    = (const float*)d_in[3];
    const float* bkv    = (const float*)d_in[4];
    const float* Wo     = (const float*)d_in[5];
    const float* bo     = (const float*)d_in[6];
    const float* convw  = (const float*)d_in[7];
    const float* convb  = (const float*)d_in[8];
    const float* gamma  = (const float*)d_in[9];
    const float* beta   = (const float*)d_in[10];
    float* out = (float*)d_out;

    const int smem_bytes = 48192 * 4;   // ~188 KB
    cudaFuncSetAttribute(attn_kernel, cudaFuncAttributeMaxDynamicSharedMemorySize, smem_bytes);

    prep_kernel<<<1088, 256>>>(Wq, Wo, Wkv, convw);
    conv_kv_kernel<<<128, 256>>>(inputs, convb, gamma, beta, bkv);
    attn_kernel<<<dim3(256, 16), 512, smem_bytes>>>(inputs, bq, bo, out);
}

// round 11
// speedup vs baseline: 1.6642x; 1.6642x over previous
#include <cuda_runtime.h>
#include <cstdint>

#define BATCH 16
#define NTOK  16384
#define CH    64
#define NKV   256

// scratch (allocation-free)
__device__ float g_k[BATCH * NKV * CH];     // K natural [b][t][d] (tf32-rounded)
__device__ float g_v[BATCH * CH * NKV];     // V transposed [b][d][t] (tf32-rounded)
__device__ float g_wqT[64 * 64];            // Wq^T [d][c] (tf32)
__device__ float g_woT[64 * 64];            // Wo^T [e][d] (tf32)
__device__ float g_wkvT[128 * 64];          // Wkv^T [o][c] (tf32)
__device__ float g_cwT[64 * 4096];          // conv_w^T [co][ij*64+ci] (tf32)

__device__ __forceinline__ uint32_t f2t(float x) {
    uint32_t u; asm("cvt.rna.tf32.f32 %0, %1;" : "=r"(u) : "f"(x)); return u;
}
__device__ __forceinline__ float f2tf(float x) { return __uint_as_float(f2t(x)); }

__device__ __forceinline__ void mma8(float* d, const uint32_t* a, const uint32_t* b) {
    asm volatile(
        "mma.sync.aligned.m16n8k8.row.col.f32.tf32.tf32.f32 "
        "{%0,%1,%2,%3},{%4,%5,%6,%7},{%8,%9},{%0,%1,%2,%3};"
        : "+f"(d[0]), "+f"(d[1]), "+f"(d[2]), "+f"(d[3])
        : "r"(a[0]), "r"(a[1]), "r"(a[2]), "r"(a[3]), "r"(b[0]), "r"(b[1]));
}
// A row-major [m][k]; pa = &A[(m0+g)*s + k0 + t4]; s8 = 8*stride
__device__ __forceinline__ void ldA(uint32_t* a, const float* pa, int s8) {
    a[0] = __float_as_uint(pa[0]);  a[1] = __float_as_uint(pa[s8]);
    a[2] = __float_as_uint(pa[4]);  a[3] = __float_as_uint(pa[s8 + 4]);
}
// B col-major [n][k]; pb = &B[(n0+g)*s + k0 + t4]
__device__ __forceinline__ void ldB(uint32_t* b, const float* pb) {
    b[0] = __float_as_uint(pb[0]);  b[1] = __float_as_uint(pb[4]);
}
// C-fragment (m16n8: rows g,g+8, cols 2t4,2t4+1) -> A-fragment (m16k8: rows
// g,g+8, cols t4,t4+4). Col t4 lives at lane (g<<2)|(t4>>1), slot t4&1; col
// t4+4 at that lane + 2.
__device__ __forceinline__ void cvtA(uint32_t* a, const float* c, int l0, int l1, int hi) {
    float v00 = __shfl_sync(0xffffffffu, c[0], l0);
    float v01 = __shfl_sync(0xffffffffu, c[1], l0);
    float v02 = __shfl_sync(0xffffffffu, c[2], l0);
    float v03 = __shfl_sync(0xffffffffu, c[3], l0);
    float v10 = __shfl_sync(0xffffffffu, c[0], l1);
    float v11 = __shfl_sync(0xffffffffu, c[1], l1);
    float v12 = __shfl_sync(0xffffffffu, c[2], l1);
    float v13 = __shfl_sync(0xffffffffu, c[3], l1);
    a[0] = __float_as_uint(hi ? v01 : v00);
    a[1] = __float_as_uint(hi ? v03 : v02);
    a[2] = __float_as_uint(hi ? v11 : v10);
    a[3] = __float_as_uint(hi ? v13 : v12);
}

// ============================================================================
// prep: transpose + tf32-round all weight matrices
// ============================================================================
__global__ __launch_bounds__(256) void prep_kernel(
    const float* __restrict__ Wq, const float* __restrict__ Wo,
    const float* __restrict__ Wkv, const float* __restrict__ cw)
{
    int i = blockIdx.x * 256 + threadIdx.x;
    if (i < 4096) {
        int d = i >> 6, c = i & 63;
        g_wqT[i] = f2tf(Wq[c * 64 + d]);
    } else if (i < 8192) {
        int j = i - 4096, e = j >> 6, d = j & 63;
        g_woT[j] = f2tf(Wo[d * 64 + e]);
    } else if (i < 16384) {
        int j = i - 8192, o = j >> 6, c = j & 63;
        g_wkvT[j] = f2tf(Wkv[c * 128 + o]);
    } else if (i < 278528) {
        int j = i - 16384, co = j >> 12, k = j & 4095;
        g_cwT[j] = f2tf(cw[k * 64 + co]);
    }
}

// ============================================================================
// Kernel 1: strided conv (8x8, s8) + bias + LN + KV proj (R6, known good)
// ============================================================================
__global__ __launch_bounds__(256) void conv_kv_kernel(
    const float* __restrict__ x, const float* __restrict__ convb,
    const float* __restrict__ gamma, const float* __restrict__ beta,
    const float* __restrict__ bkv)
{
    __shared__ float sC[32 * 68];
    __shared__ float sB[128 * 68];
    __shared__ float aux[576];

    const int tid = threadIdx.x;
    const int w = tid >> 5, lane = tid & 31, g = lane >> 2, t4 = lane & 3;
    const int t0 = blockIdx.x * 32, b = t0 >> 8;
    const int mi = w & 1, m0 = mi * 16;

    const int tt = tid & 31, ci0 = (tid >> 5) * 8;
    const int gb = (t0 + tt) & 255, ph = gb >> 4, pw = gb & 15;
    const float* xb = x + (size_t)b * NTOK * CH;

    float acc1[2][4];
    #pragma unroll
    for (int n = 0; n < 2; n++) { acc1[n][0]=acc1[n][1]=acc1[n][2]=acc1[n][3]=0.f; }

    for (int ij = 0; ij < 64; ij++) {
        __syncthreads();
        {
            const int row = ph * 8 + (ij >> 3), col = pw * 8 + (ij & 7);
            const float* xr = xb + (size_t)(row * 128 + col) * CH + ci0;
            float4 v0 = *(const float4*)xr, v1 = *(const float4*)(xr + 4);
            *(float4*)&sC[tt * 68 + ci0]     = make_float4(f2tf(v0.x), f2tf(v0.y), f2tf(v0.z), f2tf(v0.w));
            *(float4*)&sC[tt * 68 + ci0 + 4] = make_float4(f2tf(v1.x), f2tf(v1.y), f2tf(v1.z), f2tf(v1.w));
        }
        #pragma unroll
        for (int r = 0; r < 4; r++) {
            int pos = tid + r * 256, co = pos >> 4, c4 = pos & 15;
            *(float4*)&sB[co * 68 + c4 * 4] =
                *(const float4*)&g_cwT[co * 4096 + ij * 64 + c4 * 4];
        }
        __syncthreads();
        #pragma unroll
        for (int k0 = 0; k0 < 64; k0 += 8) {
            uint32_t a[4]; ldA(a, &sC[(m0 + g) * 68 + k0 + t4], 544);
            #pragma unroll
            for (int n = 0; n < 2; n++) {
                uint32_t bb[2]; ldB(bb, &sB[(((w >> 1) * 2 + n) * 8 + g) * 68 + k0 + t4]);
                mma8(acc1[n], a, bb);
            }
        }
    }
    __syncthreads();
    #pragma unroll
    for (int n = 0; n < 2; n++) {
        int c0 = ((w >> 1) * 2 + n) * 8 + 2 * t4;
        float2 bc = *(const float2*)&convb[c0];
        *(float2*)&sC[(m0 + g) * 68 + c0]     = make_float2(acc1[n][0] + bc.x, acc1[n][1] + bc.y);
        *(float2*)&sC[(m0 + g + 8) * 68 + c0] = make_float2(acc1[n][2] + bc.x, acc1[n][3] + bc.y);
    }
    __syncthreads();
    #pragma unroll
    for (int r = 0; r < 8; r++) {
        int pos = tid + r * 256, o = pos >> 4, c4 = pos & 15;
        *(float4*)&sB[o * 68 + c4 * 4] = *(const float4*)&g_wkvT[o * 64 + c4 * 4];
    }
    {
        int tok = tid & 31, pr = tid >> 5;
        float4 u0 = *(float4*)&sC[tok * 68 + pr * 8];
        float4 u1 = *(float4*)&sC[tok * 68 + pr * 8 + 4];
        float s  = u0.x + u0.y + u0.z + u0.w + u1.x + u1.y + u1.z + u1.w;
        float sq = u0.x*u0.x + u0.y*u0.y + u0.z*u0.z + u0.w*u0.w
                 + u1.x*u1.x + u1.y*u1.y + u1.z*u1.z + u1.w*u1.w;
        aux[pr * 32 + tok] = s; aux[256 + pr * 32 + tok] = sq;
    }
    __syncthreads();
    if (tid < 32) {
        float s = 0.f, sq = 0.f;
        #pragma unroll
        for (int p = 0; p < 8; p++) { s += aux[p * 32 + tid]; sq += aux[256 + p * 32 + tid]; }
        float mean = s * (1.f / 64.f);
        float var  = sq * (1.f / 64.f) - mean * mean;
        aux[512 + tid] = mean; aux[544 + tid] = rsqrtf(var + 1e-5f);
    }
    __syncthreads();
    {
        int tok = tid & 31, pr = tid >> 5;
        float mean = aux[512 + tok], r = aux[544 + tok];
        #pragma unroll
        for (int u = 0; u < 8; u++) {
            int c = pr * 8 + u;
            float v = sC[tok * 68 + c];
            sC[tok * 68 + c] = f2tf((v - mean) * r * __ldg(gamma + c) + __ldg(beta + c));
        }
    }
    __syncthreads();
    float acc2[4][4];
    #pragma unroll
    for (int n = 0; n < 4; n++) { acc2[n][0]=acc2[n][1]=acc2[n][2]=acc2[n][3]=0.f; }
    #pragma unroll
    for (int k0 = 0; k0 < 64; k0 += 8) {
        uint32_t a[4]; ldA(a, &sC[(m0 + g) * 68 + k0 + t4], 544);
        #pragma unroll
        for (int n = 0; n < 4; n++) {
            uint32_t bb[2]; ldB(bb, &sB[(((w >> 1) * 4 + n) * 8 + g) * 68 + k0 + t4]);
            mma8(acc2[n], a, bb);
        }
    }
    const int tloc = t0 & 255;
    #pragma unroll
    for (int n = 0; n < 4; n++) {
        int c0 = ((w >> 1) * 4 + n) * 8 + 2 * t4;
        float bk0 = __ldg(bkv + c0), bk1 = __ldg(bkv + c0 + 1);
        #pragma unroll
        for (int h = 0; h < 2; h++) {
            int row = m0 + g + h * 8;
            float r0 = f2tf(acc2[n][2 * h + 0] + bk0);
            float r1 = f2tf(acc2[n][2 * h + 1] + bk1);
            if (c0 < 64) {
                g_k[(size_t)(t0 + row) * 64 + c0]     = r0;
                g_k[(size_t)(t0 + row) * 64 + c0 + 1] = r1;
            } else {
                g_v[(size_t)(b * 64 + c0 - 64) * 256 + tloc + row] = r0;
                g_v[(size_t)(b * 64 + c0 - 63) * 256 + tloc + row] = r1;
            }
        }
    }
}

// ============================================================================
// Kernel 2: 64 queries/block, 4 warps (16 q-rows x full 256 kv each).
// S, P, Q, O all register-resident; fragment relayout via shuffles.
// smem: pool[0,17408): X[0,4352)+WqT[4352,8704) -> K -> Vt ; WoT[17408,21760)
// 85 KB -> 2 blocks/SM.
// ============================================================================
__global__ __launch_bounds__(128, 2) void attn_kernel(
    const float* __restrict__ x, const float* __restrict__ bq,
    const float* __restrict__ bo, float* __restrict__ out)
{
    extern __shared__ float sm[];
    float* sX  = sm;             // 64x68 during G1
    float* sWq = sm + 4352;      // 64x68 during G1
    float* sK  = sm;             // 256x68 during G2
    float* sV  = sm;             // 64x260 during G3
    float* sWo = sm + 17408;     // 64x68 (disjoint, lives whole kernel)

    const int tid = threadIdx.x;
    const int w = tid >> 5, lane = tid & 31, g = lane >> 2, t4 = lane & 3;
    const int b = blockIdx.y, q0 = blockIdx.x * 64;
    const int m0 = w * 16;
    const int hi = t4 & 1;
    const int l0 = (lane & ~3) | (t4 >> 1);
    const int l1 = l0 + 2;

    // ---- stage X (tf32-rounded) and WqT (BOTH need 1024 positions) ----
    #pragma unroll
    for (int r = 0; r < 8; r++) {
        int pos = tid + r * 128, tok = pos >> 4, c4 = pos & 15;
        float4 v = *(const float4*)&x[((size_t)(b * NTOK + q0 + tok)) * 64 + c4 * 4];
        *(float4*)&sX[tok * 68 + c4 * 4] = make_float4(f2tf(v.x), f2tf(v.y), f2tf(v.z), f2tf(v.w));
    }
    #pragma unroll
    for (int r = 0; r < 8; r++) {             // FIXED: was r < 4 (half of WqT unstaged)
        int pos = tid + r * 128, d = pos >> 4, c4 = pos & 15;
        *(float4*)&sWq[d * 68 + c4 * 4] = *(const float4*)&g_wqT[d * 64 + c4 * 4];
    }
    __syncthreads();

    // ---- G1: Q = X WqT^T  (16 rows x 64 d per warp, C-frags q[8][4]) ----
    float q[8][4];
    #pragma unroll
    for (int n = 0; n < 8; n++) { q[n][0]=q[n][1]=q[n][2]=q[n][3]=0.f; }
    #pragma unroll
    for (int k0 = 0; k0 < 64; k0 += 8) {
        uint32_t a[4]; ldA(a, &sX[(m0 + g) * 68 + k0 + t4], 544);
        #pragma unroll
        for (int n = 0; n < 8; n++) {
            uint32_t bb[2]; ldB(bb, &sWq[(n * 8 + g) * 68 + k0 + t4]);
            mma8(q[n], a, bb);
        }
    }
    // bias + 0.125 scale + tf32 round, then C->A relayout (Q never hits smem)
    uint32_t aq[8][4];
    #pragma unroll
    for (int n = 0; n < 8; n++) {
        float2 bb = *(const float2*)&bq[n * 8 + 2 * t4];
        q[n][0] = f2tf((q[n][0] + bb.x) * 0.125f);
        q[n][1] = f2tf((q[n][1] + bb.y) * 0.125f);
        q[n][2] = f2tf((q[n][2] + bb.x) * 0.125f);
        q[n][3] = f2tf((q[n][3] + bb.y) * 0.125f);
        cvtA(aq[n], q[n], l0, l1, hi);
    }
    __syncthreads();   // X/WqT dead

    // ---- stage K [j][d] (stride 68) over pool; stage WoT ----
    #pragma unroll
    for (int r = 0; r < 32; r++) {
        int pos = tid + r * 128, j = pos >> 4, c4 = pos & 15;
        *(float4*)&sK[j * 68 + c4 * 4] =
            *(const float4*)&g_k[(size_t)b * 16384 + j * 64 + c4 * 4];
    }
    #pragma unroll
    for (int r = 0; r < 8; r++) {             // FIXED: was r < 4 (half of WoT unstaged)
        int pos = tid + r * 128, e = pos >> 4, c4 = pos & 15;
        *(float4*)&sWo[e * 68 + c4 * 4] = *(const float4*)&g_woT[e * 64 + c4 * 4];
    }
    __syncthreads();

    // ---- G2: S = Q K^T (16 rows x 256 j per warp, s[32][4] in regs) ----
    float s[32][4];
    #pragma unroll
    for (int n = 0; n < 32; n++) { s[n][0]=s[n][1]=s[n][2]=s[n][3]=0.f; }
    #pragma unroll
    for (int k0 = 0; k0 < 64; k0 += 8) {
        const uint32_t* a = aq[k0 >> 3];
        #pragma unroll
        for (int n = 0; n < 32; n++) {
            uint32_t bb[2]; ldB(bb, &sK[(n * 8 + g) * 68 + k0 + t4]);
            mma8(s[n], a, bb);
        }
    }
    __syncthreads();   // K dead

    // ---- stage Vt [d][j] (stride 260) over pool (overlaps reg softmax) ----
    #pragma unroll
    for (int r = 0; r < 32; r++) {
        int pos = tid + r * 128, d = pos >> 6, j4 = pos & 63;
        *(float4*)&sV[d * 260 + j4 * 4] =
            *(const float4*)&g_v[(size_t)b * 16384 + d * 256 + j4 * 4];
    }

    // ---- register softmax: rows g (regs 0,1) and g+8 (regs 2,3) ----
    float mA = -1e30f, mB = -1e30f;
    #pragma unroll
    for (int n = 0; n < 32; n++) {
        mA = fmaxf(mA, fmaxf(s[n][0], s[n][1]));
        mB = fmaxf(mB, fmaxf(s[n][2], s[n][3]));
    }
    mA = fmaxf(mA, __shfl_xor_sync(0xffffffffu, mA, 1));
    mA = fmaxf(mA, __shfl_xor_sync(0xffffffffu, mA, 2));
    mB = fmaxf(mB, __shfl_xor_sync(0xffffffffu, mB, 1));
    mB = fmaxf(mB, __shfl_xor_sync(0xffffffffu, mB, 2));
    float sA = 0.f, sB2 = 0.f;
    #pragma unroll
    for (int n = 0; n < 32; n++) {
        s[n][0] = __expf(s[n][0] - mA); s[n][1] = __expf(s[n][1] - mA);
        s[n][2] = __expf(s[n][2] - mB); s[n][3] = __expf(s[n][3] - mB);
        sA  += s[n][0] + s[n][1];
        sB2 += s[n][2] + s[n][3];
        s[n][0] = f2tf(s[n][0]); s[n][1] = f2tf(s[n][1]);
        s[n][2] = f2tf(s[n][2]); s[n][3] = f2tf(s[n][3]);
    }
    sA  += __shfl_xor_sync(0xffffffffu, sA, 1);
    sA  += __shfl_xor_sync(0xffffffffu, sA, 2);
    sB2 += __shfl_xor_sync(0xffffffffu, sB2, 1);
    sB2 += __shfl_xor_sync(0xffffffffu, sB2, 2);
    const float ilA = 1.f / sA, ilB = 1.f / sB2;
    __syncthreads();   // Vt staged, all warps done with K

    // ---- G3: O = P Vt^T (k=256 over j), P relayout fused per k-step ----
    float o[8][4];
    #pragma unroll
    for (int n = 0; n < 8; n++) { o[n][0]=o[n][1]=o[n][2]=o[n][3]=0.f; }
    #pragma unroll
    for (int kt = 0; kt < 32; kt++) {
        const int k0 = kt * 8;
        uint32_t a[4]; cvtA(a, s[kt], l0, l1, hi);
        #pragma unroll
        for (int n = 0; n < 8; n++) {
            uint32_t bb[2]; ldB(bb, &sV[(n * 8 + g) * 260 + k0 + t4]);
            mma8(o[n], a, bb);
        }
    }
    // 1/l scale + round + relayout (O never hits smem)
    uint32_t ao[8][4];
    #pragma unroll
    for (int n = 0; n < 8; n++) {
        o[n][0] = f2tf(o[n][0] * ilA); o[n][1] = f2tf(o[n][1] * ilA);
        o[n][2] = f2tf(o[n][2] * ilB); o[n][3] = f2tf(o[n][3] * ilB);
        cvtA(ao[n], o[n], l0, l1, hi);
    }

    // ---- G4: Y = O WoT^T + bo -> gmem ----
    float y[8][4];
    #pragma unroll
    for (int n = 0; n < 8; n++) { y[n][0]=y[n][1]=y[n][2]=y[n][3]=0.f; }
    #pragma unroll
    for (int k0 = 0; k0 < 64; k0 += 8) {
        const uint32_t* a = ao[k0 >> 3];
        #pragma unroll
        for (int n = 0; n < 8; n++) {
            uint32_t bb[2]; ldB(bb, &sWo[(n * 8 + g) * 68 + k0 + t4]);
            mma8(y[n], a, bb);
        }
    }
    const size_t r0 = ((size_t)(b * NTOK + q0 + m0 + g)) * 64;
    #pragma unroll
    for (int n = 0; n < 8; n++) {
        int c0 = n * 8 + 2 * t4;
        float2 bb = *(const float2*)&bo[c0];
        *(float2*)&out[r0 + c0]          = make_float2(y[n][0] + bb.x, y[n][1] + bb.y);
        *(float2*)&out[r0 + 8 * 64 + c0] = make_float2(y[n][2] + bb.x, y[n][3] + bb.y);
    }
}

extern "C" void kernel_launch(void* const* d_in, const int* in_sizes, int n_in,
                              void* d_out, int out_size)
{
    const float* inputs = (const float*)d_in[0];
    const float* Wq     = (const float*)d_in[1];
    const float* bq     = (const float*)d_in[2];
    const float* Wkv    = (const float*)d_in[3];
    const float* bkv    = (const float*)d_in[4];
    const float* Wo     = (const float*)d_in[5];
    const float* bo     = (const float*)d_in[6];
    const float* convw  = (const float*)d_in[7];
    const float* convb  = (const float*)d_in[8];
    const float* gamma  = (const float*)d_in[9];
    const float* beta   = (const float*)d_in[10];
    float* out = (float*)d_out;

    const int smem_bytes = 21760 * 4;   // 85 KB -> 2 blocks/SM
    cudaFuncSetAttribute(attn_kernel, cudaFuncAttributeMaxDynamicSharedMemorySize, smem_bytes);

    prep_kernel<<<1088, 256>>>(Wq, Wo, Wkv, convw);
    conv_kv_kernel<<<128, 256>>>(inputs, convb, gamma, beta, bkv);
    attn_kernel<<<dim3(256, 16), 128, smem_bytes>>>(inputs, bq, bo, out);
}

// round 12
// speedup vs baseline: 1.7391x; 1.0450x over previous
#include <cuda_runtime.h>
#include <cstdint>

#define BATCH 16
#define NTOK  16384
#define CH    64
#define NKV   256

// scratch (allocation-free)
// permuted-k storage: within each 8-group, logical kk -> phys ((kk&3)<<1)|(kk>>2)
__device__ float g_k[BATCH * NKV * CH];     // K [b][t][d-perm] (tf32)
__device__ float g_v[BATCH * CH * NKV];     // Vt [b][d][t-perm] (tf32)
__device__ float g_wqT[64 * 64];            // Wq^T [d][c-perm] (tf32)
__device__ float g_woT[64 * 64];            // Wo^T [e][d-perm] (tf32)
__device__ float g_wkvT[128 * 64];          // Wkv^T [o][c] natural (conv only)
__device__ float g_cwT[64 * 4096];          // conv_w^T [co][ij*64+ci] natural

__device__ __forceinline__ int perm8(int k) {            // logical->phys within 8-group
    return (k & ~7) | (((k & 3) << 1) | ((k & 7) >> 2));
}

__device__ __forceinline__ uint32_t f2t(float x) {
    uint32_t u; asm("cvt.rna.tf32.f32 %0, %1;" : "=r"(u) : "f"(x)); return u;
}
__device__ __forceinline__ float f2tf(float x) { return __uint_as_float(f2t(x)); }

__device__ __forceinline__ void mma8(float* d, const uint32_t* a, const uint32_t* b) {
    asm volatile(
        "mma.sync.aligned.m16n8k8.row.col.f32.tf32.tf32.f32 "
        "{%0,%1,%2,%3},{%4,%5,%6,%7},{%8,%9},{%0,%1,%2,%3};"
        : "+f"(d[0]), "+f"(d[1]), "+f"(d[2]), "+f"(d[3])
        : "r"(a[0]), "r"(a[1]), "r"(a[2]), "r"(a[3]), "r"(b[0]), "r"(b[1]));
}
// natural-layout A load (scalar): pa = &A[(m0+g)*s + k0 + t4]; s8 = 8*stride
__device__ __forceinline__ void ldA(uint32_t* a, const float* pa, int s8) {
    a[0] = __float_as_uint(pa[0]);  a[1] = __float_as_uint(pa[s8]);
    a[2] = __float_as_uint(pa[4]);  a[3] = __float_as_uint(pa[s8 + 4]);
}
// natural-layout B load (scalar, conv kernel)
__device__ __forceinline__ void ldB(uint32_t* b, const float* pb) {
    b[0] = __float_as_uint(pb[0]);  b[1] = __float_as_uint(pb[4]);
}
// permuted-layout B load: one LDS.64 gives logical cols {t4, t4+4}
// pb = &B[(n*8+g)*stride + k0 + 2*t4]; stride must be == 8 (mod 32) for
// conflict-free phases (word-stride == 4 mod 16)
__device__ __forceinline__ void ldB64(uint32_t* b, const float* pb) {
    float2 v = *(const float2*)pb;
    b[0] = __float_as_uint(v.x); b[1] = __float_as_uint(v.y);
}
// C-fragment (m16n8: rows g,g+8, cols 2t4,2t4+1) -> A-fragment (m16k8: rows
// g,g+8, cols t4,t4+4). Col t4 lives at lane (g<<2)|(t4>>1), slot t4&1; col
// t4+4 at that lane + 2.
__device__ __forceinline__ void cvtA(uint32_t* a, const float* c, int l0, int l1, int hi) {
    float v00 = __shfl_sync(0xffffffffu, c[0], l0);
    float v01 = __shfl_sync(0xffffffffu, c[1], l0);
    float v02 = __shfl_sync(0xffffffffu, c[2], l0);
    float v03 = __shfl_sync(0xffffffffu, c[3], l0);
    float v10 = __shfl_sync(0xffffffffu, c[0], l1);
    float v11 = __shfl_sync(0xffffffffu, c[1], l1);
    float v12 = __shfl_sync(0xffffffffu, c[2], l1);
    float v13 = __shfl_sync(0xffffffffu, c[3], l1);
    a[0] = __float_as_uint(hi ? v01 : v00);
    a[1] = __float_as_uint(hi ? v03 : v02);
    a[2] = __float_as_uint(hi ? v11 : v10);
    a[3] = __float_as_uint(hi ? v13 : v12);
}

// ============================================================================
// prep: transpose + tf32-round weights; WqT/WoT stored k-permuted
// ============================================================================
__global__ __launch_bounds__(256) void prep_kernel(
    const float* __restrict__ Wq, const float* __restrict__ Wo,
    const float* __restrict__ Wkv, const float* __restrict__ cw)
{
    int i = blockIdx.x * 256 + threadIdx.x;
    if (i < 4096) {
        int d = i >> 6, c = i & 63;
        g_wqT[d * 64 + perm8(c)] = f2tf(Wq[c * 64 + d]);
    } else if (i < 8192) {
        int j = i - 4096, e = j >> 6, d = j & 63;
        g_woT[e * 64 + perm8(d)] = f2tf(Wo[d * 64 + e]);
    } else if (i < 16384) {
        int j = i - 8192;                       // natural (conv consumes it)
        int o = j >> 6, c = j & 63;
        g_wkvT[j] = f2tf(Wkv[c * 128 + o]);
    } else if (i < 278528) {
        int j = i - 16384, co = j >> 12, k = j & 4095;
        g_cwT[j] = f2tf(cw[k * 64 + co]);
    }
}

// ============================================================================
// Kernel 1: strided conv (8x8, s8) + bias + LN + KV proj (R6 core; epilogue
// now writes g_k / g_v in permuted-k layout — same store count)
// ============================================================================
__global__ __launch_bounds__(256) void conv_kv_kernel(
    const float* __restrict__ x, const float* __restrict__ convb,
    const float* __restrict__ gamma, const float* __restrict__ beta,
    const float* __restrict__ bkv)
{
    __shared__ float sC[32 * 68];
    __shared__ float sB[128 * 68];
    __shared__ float aux[576];

    const int tid = threadIdx.x;
    const int w = tid >> 5, lane = tid & 31, g = lane >> 2, t4 = lane & 3;
    const int t0 = blockIdx.x * 32, b = t0 >> 8;
    const int mi = w & 1, m0 = mi * 16;

    const int tt = tid & 31, ci0 = (tid >> 5) * 8;
    const int gb = (t0 + tt) & 255, ph = gb >> 4, pw = gb & 15;
    const float* xb = x + (size_t)b * NTOK * CH;

    float acc1[2][4];
    #pragma unroll
    for (int n = 0; n < 2; n++) { acc1[n][0]=acc1[n][1]=acc1[n][2]=acc1[n][3]=0.f; }

    for (int ij = 0; ij < 64; ij++) {
        __syncthreads();
        {
            const int row = ph * 8 + (ij >> 3), col = pw * 8 + (ij & 7);
            const float* xr = xb + (size_t)(row * 128 + col) * CH + ci0;
            float4 v0 = *(const float4*)xr, v1 = *(const float4*)(xr + 4);
            *(float4*)&sC[tt * 68 + ci0]     = make_float4(f2tf(v0.x), f2tf(v0.y), f2tf(v0.z), f2tf(v0.w));
            *(float4*)&sC[tt * 68 + ci0 + 4] = make_float4(f2tf(v1.x), f2tf(v1.y), f2tf(v1.z), f2tf(v1.w));
        }
        #pragma unroll
        for (int r = 0; r < 4; r++) {
            int pos = tid + r * 256, co = pos >> 4, c4 = pos & 15;
            *(float4*)&sB[co * 68 + c4 * 4] =
                *(const float4*)&g_cwT[co * 4096 + ij * 64 + c4 * 4];
        }
        __syncthreads();
        #pragma unroll
        for (int k0 = 0; k0 < 64; k0 += 8) {
            uint32_t a[4]; ldA(a, &sC[(m0 + g) * 68 + k0 + t4], 544);
            #pragma unroll
            for (int n = 0; n < 2; n++) {
                uint32_t bb[2]; ldB(bb, &sB[(((w >> 1) * 2 + n) * 8 + g) * 68 + k0 + t4]);
                mma8(acc1[n], a, bb);
            }
        }
    }
    __syncthreads();
    #pragma unroll
    for (int n = 0; n < 2; n++) {
        int c0 = ((w >> 1) * 2 + n) * 8 + 2 * t4;
        float2 bc = *(const float2*)&convb[c0];
        *(float2*)&sC[(m0 + g) * 68 + c0]     = make_float2(acc1[n][0] + bc.x, acc1[n][1] + bc.y);
        *(float2*)&sC[(m0 + g + 8) * 68 + c0] = make_float2(acc1[n][2] + bc.x, acc1[n][3] + bc.y);
    }
    __syncthreads();
    #pragma unroll
    for (int r = 0; r < 8; r++) {
        int pos = tid + r * 256, o = pos >> 4, c4 = pos & 15;
        *(float4*)&sB[o * 68 + c4 * 4] = *(const float4*)&g_wkvT[o * 64 + c4 * 4];
    }
    {
        int tok = tid & 31, pr = tid >> 5;
        float4 u0 = *(float4*)&sC[tok * 68 + pr * 8];
        float4 u1 = *(float4*)&sC[tok * 68 + pr * 8 + 4];
        float s  = u0.x + u0.y + u0.z + u0.w + u1.x + u1.y + u1.z + u1.w;
        float sq = u0.x*u0.x + u0.y*u0.y + u0.z*u0.z + u0.w*u0.w
                 + u1.x*u1.x + u1.y*u1.y + u1.z*u1.z + u1.w*u1.w;
        aux[pr * 32 + tok] = s; aux[256 + pr * 32 + tok] = sq;
    }
    __syncthreads();
    if (tid < 32) {
        float s = 0.f, sq = 0.f;
        #pragma unroll
        for (int p = 0; p < 8; p++) { s += aux[p * 32 + tid]; sq += aux[256 + p * 32 + tid]; }
        float mean = s * (1.f / 64.f);
        float var  = sq * (1.f / 64.f) - mean * mean;
        aux[512 + tid] = mean; aux[544 + tid] = rsqrtf(var + 1e-5f);
    }
    __syncthreads();
    {
        int tok = tid & 31, pr = tid >> 5;
        float mean = aux[512 + tok], r = aux[544 + tok];
        #pragma unroll
        for (int u = 0; u < 8; u++) {
            int c = pr * 8 + u;
            float v = sC[tok * 68 + c];
            sC[tok * 68 + c] = f2tf((v - mean) * r * __ldg(gamma + c) + __ldg(beta + c));
        }
    }
    __syncthreads();
    float acc2[4][4];
    #pragma unroll
    for (int n = 0; n < 4; n++) { acc2[n][0]=acc2[n][1]=acc2[n][2]=acc2[n][3]=0.f; }
    #pragma unroll
    for (int k0 = 0; k0 < 64; k0 += 8) {
        uint32_t a[4]; ldA(a, &sC[(m0 + g) * 68 + k0 + t4], 544);
        #pragma unroll
        for (int n = 0; n < 4; n++) {
            uint32_t bb[2]; ldB(bb, &sB[(((w >> 1) * 4 + n) * 8 + g) * 68 + k0 + t4]);
            mma8(acc2[n], a, bb);
        }
    }
    const int tloc = t0 & 255;
    #pragma unroll
    for (int n = 0; n < 4; n++) {
        int c0 = ((w >> 1) * 4 + n) * 8 + 2 * t4;
        float bk0 = __ldg(bkv + c0), bk1 = __ldg(bkv + c0 + 1);
        #pragma unroll
        for (int h = 0; h < 2; h++) {
            int row = m0 + g + h * 8;
            float r0 = f2tf(acc2[n][2 * h + 0] + bk0);
            float r1 = f2tf(acc2[n][2 * h + 1] + bk1);
            if (c0 < 64) {   // K [t][d-perm]
                g_k[(size_t)(t0 + row) * 64 + perm8(c0)]     = r0;
                g_k[(size_t)(t0 + row) * 64 + perm8(c0 + 1)] = r1;
            } else {         // Vt [d][t-perm]
                int pt = perm8(tloc + row);
                g_v[(size_t)(b * 64 + c0 - 64) * 256 + pt] = r0;
                g_v[(size_t)(b * 64 + c0 - 63) * 256 + pt] = r1;
            }
        }
    }
}

// ============================================================================
// Kernel 2: 64 queries/block, 4 warps (16 q-rows x full 256 kv each).
// S/P/Q/O register-resident; B-operands permuted-k, single LDS.64 per frag.
// smem pool[0,18432): X(4352)+Wq(4608) -> K(256x72) -> Vt(64x264);
// Wo at [18432,23040). 90 KB -> 2 blocks/SM.
// ============================================================================
__global__ __launch_bounds__(128, 2) void attn_kernel(
    const float* __restrict__ x, const float* __restrict__ bq,
    const float* __restrict__ bo, float* __restrict__ out)
{
    extern __shared__ float sm[];
    float* sX  = sm;             // 64x68 natural (G1 A)
    float* sWq = sm + 4352;      // 64x72 perm (G1 B)
    float* sK  = sm;             // 256x72 perm (G2 B)
    float* sV  = sm;             // 64x264 perm (G3 B)
    float* sWo = sm + 18432;     // 64x72 perm (G4 B), disjoint

    const int tid = threadIdx.x;
    const int w = tid >> 5, lane = tid & 31, g = lane >> 2, t4 = lane & 3;
    const int b = blockIdx.y, q0 = blockIdx.x * 64;
    const int m0 = w * 16;
    const int hi = t4 & 1;
    const int l0 = (lane & ~3) | (t4 >> 1);
    const int l1 = l0 + 2;

    // ---- stage X (tf32-rounded, natural) and WqT (already permuted) ----
    #pragma unroll
    for (int r = 0; r < 8; r++) {
        int pos = tid + r * 128, tok = pos >> 4, c4 = pos & 15;
        float4 v = *(const float4*)&x[((size_t)(b * NTOK + q0 + tok)) * 64 + c4 * 4];
        *(float4*)&sX[tok * 68 + c4 * 4] = make_float4(f2tf(v.x), f2tf(v.y), f2tf(v.z), f2tf(v.w));
    }
    #pragma unroll
    for (int r = 0; r < 8; r++) {
        int pos = tid + r * 128, d = pos >> 4, c4 = pos & 15;
        *(float4*)&sWq[d * 72 + c4 * 4] = *(const float4*)&g_wqT[d * 64 + c4 * 4];
    }
    __syncthreads();

    // ---- G1: Q = X WqT^T  (16 rows x 64 d per warp, C-frags q[8][4]) ----
    float q[8][4];
    #pragma unroll
    for (int n = 0; n < 8; n++) { q[n][0]=q[n][1]=q[n][2]=q[n][3]=0.f; }
    #pragma unroll
    for (int k0 = 0; k0 < 64; k0 += 8) {
        uint32_t a[4]; ldA(a, &sX[(m0 + g) * 68 + k0 + t4], 544);
        #pragma unroll
        for (int n = 0; n < 8; n++) {
            uint32_t bb[2]; ldB64(bb, &sWq[(n * 8 + g) * 72 + k0 + 2 * t4]);
            mma8(q[n], a, bb);
        }
    }
    // bias + 0.125 scale + tf32 round, then C->A relayout (Q never hits smem)
    uint32_t aq[8][4];
    #pragma unroll
    for (int n = 0; n < 8; n++) {
        float2 bb = *(const float2*)&bq[n * 8 + 2 * t4];
        q[n][0] = f2tf((q[n][0] + bb.x) * 0.125f);
        q[n][1] = f2tf((q[n][1] + bb.y) * 0.125f);
        q[n][2] = f2tf((q[n][2] + bb.x) * 0.125f);
        q[n][3] = f2tf((q[n][3] + bb.y) * 0.125f);
        cvtA(aq[n], q[n], l0, l1, hi);
    }
    __syncthreads();   // X/WqT dead

    // ---- stage K [j][d-perm] stride 72; stage WoT [e][d-perm] ----
    #pragma unroll
    for (int r = 0; r < 32; r++) {
        int pos = tid + r * 128, j = pos >> 4, c4 = pos & 15;
        *(float4*)&sK[j * 72 + c4 * 4] =
            *(const float4*)&g_k[(size_t)b * 16384 + j * 64 + c4 * 4];
    }
    #pragma unroll
    for (int r = 0; r < 8; r++) {
        int pos = tid + r * 128, e = pos >> 4, c4 = pos & 15;
        *(float4*)&sWo[e * 72 + c4 * 4] = *(const float4*)&g_woT[e * 64 + c4 * 4];
    }
    __syncthreads();

    // ---- G2: S = Q K^T (16 rows x 256 j per warp, s[32][4] in regs) ----
    float s[32][4];
    #pragma unroll
    for (int n = 0; n < 32; n++) { s[n][0]=s[n][1]=s[n][2]=s[n][3]=0.f; }
    #pragma unroll
    for (int k0 = 0; k0 < 64; k0 += 8) {
        const uint32_t* a = aq[k0 >> 3];
        #pragma unroll
        for (int n = 0; n < 32; n++) {
            uint32_t bb[2]; ldB64(bb, &sK[(n * 8 + g) * 72 + k0 + 2 * t4]);
            mma8(s[n], a, bb);
        }
    }
    __syncthreads();   // K dead

    // ---- stage Vt [d][j-perm] stride 264 over pool ----
    #pragma unroll
    for (int r = 0; r < 32; r++) {
        int pos = tid + r * 128, d = pos >> 6, j4 = pos & 63;
        *(float4*)&sV[d * 264 + j4 * 4] =
            *(const float4*)&g_v[(size_t)b * 16384 + d * 256 + j4 * 4];
    }

    // ---- register softmax: rows g (regs 0,1) and g+8 (regs 2,3) ----
    float mA = -1e30f, mB = -1e30f;
    #pragma unroll
    for (int n = 0; n < 32; n++) {
        mA = fmaxf(mA, fmaxf(s[n][0], s[n][1]));
        mB = fmaxf(mB, fmaxf(s[n][2], s[n][3]));
    }
    mA = fmaxf(mA, __shfl_xor_sync(0xffffffffu, mA, 1));
    mA = fmaxf(mA, __shfl_xor_sync(0xffffffffu, mA, 2));
    mB = fmaxf(mB, __shfl_xor_sync(0xffffffffu, mB, 1));
    mB = fmaxf(mB, __shfl_xor_sync(0xffffffffu, mB, 2));
    float sA = 0.f, sB2 = 0.f;
    #pragma unroll
    for (int n = 0; n < 32; n++) {
        s[n][0] = __expf(s[n][0] - mA); s[n][1] = __expf(s[n][1] - mA);
        s[n][2] = __expf(s[n][2] - mB); s[n][3] = __expf(s[n][3] - mB);
        sA  += s[n][0] + s[n][1];
        sB2 += s[n][2] + s[n][3];
        s[n][0] = f2tf(s[n][0]); s[n][1] = f2tf(s[n][1]);
        s[n][2] = f2tf(s[n][2]); s[n][3] = f2tf(s[n][3]);
    }
    sA  += __shfl_xor_sync(0xffffffffu, sA, 1);
    sA  += __shfl_xor_sync(0xffffffffu, sA, 2);
    sB2 += __shfl_xor_sync(0xffffffffu, sB2, 1);
    sB2 += __shfl_xor_sync(0xffffffffu, sB2, 2);
    const float ilA = 1.f / sA, ilB = 1.f / sB2;
    __syncthreads();   // Vt staged, all warps done with K

    // ---- G3: O = P Vt^T (k=256 over j), P relayout fused per k-step ----
    float o[8][4];
    #pragma unroll
    for (int n = 0; n < 8; n++) { o[n][0]=o[n][1]=o[n][2]=o[n][3]=0.f; }
    #pragma unroll
    for (int kt = 0; kt < 32; kt++) {
        const int k0 = kt * 8;
        uint32_t a[4]; cvtA(a, s[kt], l0, l1, hi);
        #pragma unroll
        for (int n = 0; n < 8; n++) {
            uint32_t bb[2]; ldB64(bb, &sV[(n * 8 + g) * 264 + k0 + 2 * t4]);
            mma8(o[n], a, bb);
        }
    }
    // 1/l scale + round + relayout (O never hits smem)
    uint32_t ao[8][4];
    #pragma unroll
    for (int n = 0; n < 8; n++) {
        o[n][0] = f2tf(o[n][0] * ilA); o[n][1] = f2tf(o[n][1] * ilA);
        o[n][2] = f2tf(o[n][2] * ilB); o[n][3] = f2tf(o[n][3] * ilB);
        cvtA(ao[n], o[n], l0, l1, hi);
    }

    // ---- G4: Y = O WoT^T + bo -> gmem ----
    float y[8][4];
    #pragma unroll
    for (int n = 0; n < 8; n++) { y[n][0]=y[n][1]=y[n][2]=y[n][3]=0.f; }
    #pragma unroll
    for (int k0 = 0; k0 < 64; k0 += 8) {
        const uint32_t* a = ao[k0 >> 3];
        #pragma unroll
        for (int n = 0; n < 8; n++) {
            uint32_t bb[2]; ldB64(bb, &sWo[(n * 8 + g) * 72 + k0 + 2 * t4]);
            mma8(y[n], a, bb);
        }
    }
    const size_t r0 = ((size_t)(b * NTOK + q0 + m0 + g)) * 64;
    #pragma unroll
    for (int n = 0; n < 8; n++) {
        int c0 = n * 8 + 2 * t4;
        float2 bb = *(const float2*)&bo[c0];
        *(float2*)&out[r0 + c0]          = make_float2(y[n][0] + bb.x, y[n][1] + bb.y);
        *(float2*)&out[r0 + 8 * 64 + c0] = make_float2(y[n][2] + bb.x, y[n][3] + bb.y);
    }
}

extern "C" void kernel_launch(void* const* d_in, const int* in_sizes, int n_in,
                              void* d_out, int out_size)
{
    const float* inputs = (const float*)d_in[0];
    const float* Wq     = (const float*)d_in[1];
    const float* bq     = (const float*)d_in[2];
    const float* Wkv    = (const float*)d_in[3];
    const float* bkv    = (const float*)d_in[4];
    const float* Wo     = (const float*)d_in[5];
    const float* bo     = (const float*)d_in[6];
    const float* convw  = (const float*)d_in[7];
    const float* convb  = (const float*)d_in[8];
    const float* gamma  = (const float*)d_in[9];
    const float* beta   = (const float*)d_in[10];
    float* out = (float*)d_out;

    const int smem_bytes = 23040 * 4;   // 90 KB -> 2 blocks/SM
    cudaFuncSetAttribute(attn_kernel, cudaFuncAttributeMaxDynamicSharedMemorySize, smem_bytes);

    prep_kernel<<<1088, 256>>>(Wq, Wo, Wkv, convw);
    conv_kv_kernel<<<128, 256>>>(inputs, convb, gamma, beta, bkv);
    attn_kernel<<<dim3(256, 16), 128, smem_bytes>>>(inputs, bq, bo, out);
}